// round 13
// baseline (speedup 1.0000x reference)
#include <cuda_runtime.h>
#include <math.h>
#include <stdint.h>

#define BB 4
#define SQ 2048
#define EE 1024
#define HH 16
#define DH 64
#define ROWS 16
#define KT 128

#define GM (BB*SQ)     // 8192
#define GN (3*EE)      // 3072
#define GK (EE)        // 1024

// GEMM tiling
#define TM 128
#define TN 128
#define TKS 32
#define PAD 36
#define ABUF (TM*PAD)

#define SCP 2052       // sc row pitch (mod 32 banks = 4)
#define KTP 8704       // K tile buffer stride (128*68)
#define VTP 8704       // V tile buffer stride (64*132 = 8448, padded)

// Scratch
__device__ float g_q[(size_t)BB * HH * SQ * DH];
__device__ float g_k[(size_t)BB * HH * SQ * DH];
__device__ float g_v[(size_t)BB * HH * DH * SQ];
__device__ float g_xr[(size_t)GM * GK];     // tf32-rounded x
__device__ float g_wr[(size_t)GN * GK];     // tf32-rounded W

__device__ __forceinline__ uint32_t f2tf32(float x) {
    uint32_t r;
    asm("cvt.rna.tf32.f32 %0, %1;" : "=r"(r) : "f"(x));
    return r;
}
__device__ __forceinline__ float tf32r(float x) { return __uint_as_float(f2tf32(x)); }

#define MMA_TF32(acc, a0, a1, a2, a3, b0, b1)                                \
    asm volatile(                                                            \
        "mma.sync.aligned.m16n8k8.row.col.f32.tf32.tf32.f32 "                \
        "{%0,%1,%2,%3}, {%4,%5,%6,%7}, {%8,%9}, {%0,%1,%2,%3};\n"            \
        : "+f"(acc[0]), "+f"(acc[1]), "+f"(acc[2]), "+f"(acc[3])             \
        : "r"(a0), "r"(a1), "r"(a2), "r"(a3), "r"(b0), "r"(b1))

#define CP_ASYNC16(dst, src) \
    asm volatile("cp.async.cg.shared.global [%0], [%1], 16;\n" :: "r"(dst), "l"(src))
#define CP_COMMIT()  asm volatile("cp.async.commit_group;\n" ::)
#define CP_WAIT(n)   asm volatile("cp.async.wait_group %0;\n" :: "n"(n))

// ---------------------------------------------------------------------------
// Pre-round input arrays to tf32 (numerically identical to in-loop cvt).
// ---------------------------------------------------------------------------
__global__ __launch_bounds__(256) void round_tf32_kernel(
    const float* __restrict__ in, float* __restrict__ out, int n4)
{
    int i = blockIdx.x * 256 + threadIdx.x;
    if (i < n4) {
        float4 v = ((const float4*)in)[i];
        v.x = tf32r(v.x); v.y = tf32r(v.y); v.z = tf32r(v.z); v.w = tf32r(v.w);
        ((float4*)out)[i] = v;
    }
}

// ---------------------------------------------------------------------------
// QKV GEMM (TF32): qkv = xr @ Wr^T (pre-rounded), scatter into g_k/g_q/g_v.
// Raw fragment loads, single-barrier pipelined mainloop.
// ---------------------------------------------------------------------------
__global__ __launch_bounds__(256, 2) void qkv_gemm_tf32(
    const float* __restrict__ A, const float* __restrict__ W,
    float* __restrict__ gq, float* __restrict__ gk, float* __restrict__ gv)
{
    extern __shared__ float gs[];
    float* As = gs;
    float* Bs = gs + 2 * ABUF;

    const int tid  = threadIdx.x;
    const int lane = tid & 31;
    const int wid  = tid >> 5;
    const int wm   = wid & 3;
    const int wn   = wid >> 2;
    const int g    = lane >> 2;
    const int tig  = lane & 3;
    const int m0   = blockIdx.y * TM;
    const int n0   = blockIdx.x * TN;

    const uint32_t s_base = (uint32_t)__cvta_generic_to_shared(gs);

    float acc[2][8][4] = {};

    auto issue = [&](int s, int buf) {
        const int k0 = s * TKS;
        #pragma unroll
        for (int i = 0; i < 4; i++) {
            int c   = tid + i * 256;
            int row = c >> 3;
            int kc  = (c & 7) * 4;
            const float* srcA = A + (size_t)(m0 + row) * GK + k0 + kc;
            uint32_t dstA = s_base + (uint32_t)(buf * ABUF + row * PAD + kc) * 4u;
            CP_ASYNC16(dstA, srcA);
            const float* srcB = W + (size_t)(n0 + row) * GK + k0 + kc;
            uint32_t dstB = s_base + (uint32_t)(2 * ABUF * 4u) + (uint32_t)(buf * ABUF + row * PAD + kc) * 4u;
            CP_ASYNC16(dstB, srcB);
        }
        CP_COMMIT();
    };

    const int NS = GK / TKS;
    issue(0, 0);

    for (int s = 0; s < NS; s++) {
        const int cur = s & 1;
        CP_WAIT(0);
        __syncthreads();                       // fill(s) visible; all warps done with buf cur^1
        if (s + 1 < NS) issue(s + 1, cur ^ 1); // overlaps with MMA below

        const float* Ab = As + cur * ABUF + (wm * 32) * PAD;
        const float* Bb = Bs + cur * ABUF + (wn * 64) * PAD;

        #pragma unroll
        for (int kk = 0; kk < TKS; kk += 8) {
            uint32_t bf[8][2];
            #pragma unroll
            for (int nt = 0; nt < 8; nt++) {
                bf[nt][0] = __float_as_uint(Bb[(nt * 8 + g) * PAD + kk + tig]);
                bf[nt][1] = __float_as_uint(Bb[(nt * 8 + g) * PAD + kk + tig + 4]);
            }
            #pragma unroll
            for (int mt = 0; mt < 2; mt++) {
                uint32_t af[4];
                af[0] = __float_as_uint(Ab[(mt * 16 + g) * PAD     + kk + tig]);
                af[1] = __float_as_uint(Ab[(mt * 16 + g + 8) * PAD + kk + tig]);
                af[2] = __float_as_uint(Ab[(mt * 16 + g) * PAD     + kk + tig + 4]);
                af[3] = __float_as_uint(Ab[(mt * 16 + g + 8) * PAD + kk + tig + 4]);
                #pragma unroll
                for (int nt = 0; nt < 8; nt++)
                    MMA_TF32(acc[mt][nt], af[0], af[1], af[2], af[3], bf[nt][0], bf[nt][1]);
            }
        }
    }

    // epilogue: tf32-round, scatter to g_k (chunk 0), g_q (chunk 1), g_v^T (chunk 2)
    #pragma unroll
    for (int mt = 0; mt < 2; mt++) {
        #pragma unroll
        for (int nt = 0; nt < 8; nt++) {
            const int cc    = n0 + wn * 64 + nt * 8 + 2 * tig;
            const int chunk = cc >> 10;
            const int hd    = (cc & 1023) >> 6;
            const int d     = cc & 63;
            #pragma unroll
            for (int half = 0; half < 2; half++) {
                const int r = m0 + wm * 32 + mt * 16 + g + half * 8;
                const int b = r >> 11, srow = r & 2047;
                const float c0 = tf32r(acc[mt][nt][half * 2 + 0]);
                const float c1 = tf32r(acc[mt][nt][half * 2 + 1]);
                const size_t bh = (size_t)(b * HH + hd);
                if (chunk == 0) {
                    *(float2*)&gk[(bh * SQ + srow) * DH + d] = make_float2(c0, c1);
                } else if (chunk == 1) {
                    *(float2*)&gq[(bh * SQ + srow) * DH + d] = make_float2(c0, c1);
                } else {
                    gv[(bh * DH + d) * SQ + srow]     = c0;
                    gv[(bh * DH + d + 1) * SQ + srow] = c1;
                }
            }
        }
    }
}

// ---------------------------------------------------------------------------
// Fused causal ALiBi attention, TF32 MMA, cp.async double-buffered,
// single-barrier pipelined, strength-reduced fills.
// One CTA per (b, h, 16-row query tile). 512 threads = 16 warps.
// ---------------------------------------------------------------------------
__global__ __launch_bounds__(512, 1) void attn_kernel(
    const float* __restrict__ gq, const float* __restrict__ gk,
    const float* __restrict__ gv, float* __restrict__ out,
    float* __restrict__ attn, int write_attn)
{
    extern __shared__ float smem[];
    float* sc   = smem;                    // 16 * SCP
    float* kq   = sc + ROWS * SCP;         // 2*KTP = 17408 floats
    float* qs   = kq + 2 * KTP;            // 16 * 68
    float* sinv = qs + ROWS * 68;          // 16

    const uint32_t s_kq = (uint32_t)__cvta_generic_to_shared(kq);

    const int i0 = (gridDim.x - 1 - blockIdx.x) * ROWS;   // longest tiles first
    const int h  = blockIdx.y;
    const int b  = blockIdx.z;
    const int tid  = threadIdx.x;
    const int lane = tid & 31;
    const int w    = tid >> 5;             // warp 0..15
    const int g    = lane >> 2;            // 0..7
    const int tig  = lane & 3;             // 0..3

    const size_t bh   = (size_t)(b * HH + h);
    const float slope = exp2f(-0.5f * (float)(h + 1));
    const float inv_scale = 1.0f / 32.0f;

    const int jend   = ((i0 + ROWS - 1) / 64 + 1) * 64;   // multiple of 64
    const int ntiles = (jend + KT - 1) / KT;

    // strength-reduced per-thread fill bases
    const float*  gk_base = gk + bh * SQ * DH + tid * 4;           // linear in idx for full K tile
    const uint32_t kdst0  = s_kq + (uint32_t)(((tid >> 4) * 68 + (tid & 15) * 4)) * 4u;
    const float*  gv_base = gv + (bh * DH + (tid >> 5)) * SQ + (tid & 31) * 4;
    const uint32_t vdst0  = s_kq + (uint32_t)(((tid >> 5) * 132 + (tid & 31) * 4)) * 4u;

    auto fill_k = [&](int t, int buf) {
        const int jt = t * KT;
        const int ktile = min(KT, jend - jt);
        if (ktile == KT) {
            const float* src = gk_base + jt * DH;
            uint32_t dst = kdst0 + (uint32_t)(buf * KTP) * 4u;
            #pragma unroll
            for (int i = 0; i < 4; i++) {
                CP_ASYNC16(dst, src);
                dst += 32u * 68u * 4u;
                src += 2048;
            }
        } else {   // 64-key tail
            const float* src = gk_base + jt * DH;
            uint32_t dst = kdst0 + (uint32_t)(buf * KTP) * 4u;
            #pragma unroll
            for (int i = 0; i < 2; i++) {
                CP_ASYNC16(dst, src);
                dst += 32u * 68u * 4u;
                src += 2048;
            }
        }
        CP_COMMIT();
    };
    auto fill_v = [&](int t, int buf) {
        const int jt = t * KT;
        const int ktile = min(KT, jend - jt);
        if (ktile == KT) {
            const float* src = gv_base + jt;
            uint32_t dst = vdst0 + (uint32_t)(buf * VTP) * 4u;
            #pragma unroll
            for (int i = 0; i < 4; i++) {
                CP_ASYNC16(dst, src);
                dst += 16u * 132u * 4u;
                src += 16 * SQ;
            }
        } else {   // 64-key tail: 64 dims x 16 float4s
            for (int idx = tid; idx < 64 * 16; idx += 512) {
                int d = idx >> 4, jc = (idx & 15) * 4;
                CP_ASYNC16(s_kq + (uint32_t)(buf * VTP + d * 132 + jc) * 4u,
                           &gv[(bh * DH + d) * SQ + jt + jc]);
            }
        }
        CP_COMMIT();
    };

    // kick off first K tile immediately (overlaps with Q load)
    fill_k(0, 0);

    // --- load Q (16 x 64), pre-rounded tf32 ---
    if (tid < 256) {
        int r = tid >> 4, dc = (tid & 15) * 4;
        float4 v = *(const float4*)&gq[(bh * SQ + i0 + r) * DH + dc];
        *(float4*)&qs[r * 68 + dc] = v;
    }
    __syncthreads();

    // --- preload Q fragments (rows g, g+8), raw bits ---
    uint32_t qa[8][4];
    #pragma unroll
    for (int kk = 0; kk < 8; kk++) {
        qa[kk][0] = __float_as_uint(qs[g * 68       + kk * 8 + tig]);
        qa[kk][1] = __float_as_uint(qs[(g + 8) * 68 + kk * 8 + tig]);
        qa[kk][2] = __float_as_uint(qs[g * 68       + kk * 8 + tig + 4]);
        qa[kk][3] = __float_as_uint(qs[(g + 8) * 68 + kk * 8 + tig + 4]);
    }

    // ======================= scores (MMA, single-barrier pipeline) ===========
    for (int t = 0; t < ntiles; t++) {
        const int cur = t & 1;
        const int jt  = t * KT;
        const int ktile = min(KT, jend - jt);
        CP_WAIT(0);
        __syncthreads();                          // fill(t) visible; buf cur^1 free
        if (t + 1 < ntiles) fill_k(t + 1, cur ^ 1);

        if (w * 8 < ktile) {
            const float* ktb = kq + cur * KTP + (w * 8 + g) * 68;
            float acc[4] = {};
            #pragma unroll
            for (int kk = 0; kk < 8; kk++) {
                uint32_t b0 = __float_as_uint(ktb[kk * 8 + tig]);
                uint32_t b1 = __float_as_uint(ktb[kk * 8 + tig + 4]);
                MMA_TF32(acc, qa[kk][0], qa[kk][1], qa[kk][2], qa[kk][3], b0, b1);
            }
            const int j0 = jt + w * 8 + 2 * tig;
            #pragma unroll
            for (int half = 0; half < 2; half++) {
                const int row = g + half * 8;
                const int gi  = i0 + row;
                float v0 = (j0     <= gi) ? fmaf(slope, (float)(j0 - gi),     acc[half*2+0] * inv_scale) : -INFINITY;
                float v1 = (j0 + 1 <= gi) ? fmaf(slope, (float)(j0 + 1 - gi), acc[half*2+1] * inv_scale) : -INFINITY;
                *(float2*)&sc[row * SCP + j0] = make_float2(v0, v1);
            }
        }
    }

    __syncthreads();            // all score MMA reads done before V fill reuses kq
    fill_v(0, 0);               // lands while softmax runs

    // ======================= softmax (warp w owns row w) =======================
    {
        float* row = sc + w * SCP;
        float mx = -INFINITY;
        for (int j = lane * 4; j < jend; j += 128) {
            float4 v = *(const float4*)(row + j);
            mx = fmaxf(mx, fmaxf(fmaxf(v.x, v.y), fmaxf(v.z, v.w)));
        }
        #pragma unroll
        for (int o = 16; o; o >>= 1) mx = fmaxf(mx, __shfl_xor_sync(0xffffffffu, mx, o));
        float sum = 0.f;
        for (int j = lane * 4; j < jend; j += 128) {
            float4 v = *(const float4*)(row + j);
            v.x = __expf(v.x - mx); v.y = __expf(v.y - mx);
            v.z = __expf(v.z - mx); v.w = __expf(v.w - mx);
            *(float4*)(row + j) = v;
            sum += v.x + v.y + v.z + v.w;
        }
        #pragma unroll
        for (int o = 16; o; o >>= 1) sum += __shfl_xor_sync(0xffffffffu, sum, o);
        const float inv = 1.0f / sum;
        if (lane == 0) sinv[w] = inv;

        if (write_attn) {
            float* arow = attn + (bh * SQ + i0 + w) * SQ;
            for (int j = lane * 4; j < jend; j += 128) {
                float4 v = *(const float4*)(row + j);
                v.x *= inv; v.y *= inv; v.z *= inv; v.w *= inv;
                *(float4*)(arow + j) = v;
            }
            const float4 z = make_float4(0.f, 0.f, 0.f, 0.f);
            for (int j = jend + lane * 4; j < SQ; j += 128)
                *(float4*)(arow + j) = z;
        }
    }

    // ======================= PV (MMA, single-barrier pipeline) =======================
    // warps: ks2 = w>>1 (8 key slabs of 16), ng = w&1 (d half of 32).
    const int ks2 = w >> 1;
    const int ng  = w & 1;
    float pacc[4][4] = {};

    for (int t = 0; t < ntiles; t++) {
        const int cur = t & 1;
        const int jt  = t * KT;
        const int ktile = min(KT, jend - jt);
        CP_WAIT(0);
        __syncthreads();                          // fill_v(t) visible; buf cur^1 free; sc ready (t=0)
        if (t + 1 < ntiles) fill_v(t + 1, cur ^ 1);

        const int kb2 = ks2 * 16;
        if (kb2 < ktile) {
            const float* vtb = kq + cur * VTP;
            #pragma unroll
            for (int kk2 = 0; kk2 < 2; kk2++) {
                const int kloc = kb2 + kk2 * 8;
                uint32_t af0 = f2tf32(sc[g * SCP       + jt + kloc + tig]);
                uint32_t af1 = f2tf32(sc[(g + 8) * SCP + jt + kloc + tig]);
                uint32_t af2 = f2tf32(sc[g * SCP       + jt + kloc + tig + 4]);
                uint32_t af3 = f2tf32(sc[(g + 8) * SCP + jt + kloc + tig + 4]);
                #pragma unroll
                for (int nt = 0; nt < 4; nt++) {
                    const int d = ng * 32 + nt * 8 + g;
                    uint32_t b0 = __float_as_uint(vtb[d * 132 + kloc + tig]);
                    uint32_t b1 = __float_as_uint(vtb[d * 132 + kloc + tig + 4]);
                    MMA_TF32(pacc[nt], af0, af1, af2, af3, b0, b1);
                }
            }
        }
    }

    // --- reduce partials across the 8 key-slab warps (overlay on kq) ---
    __syncthreads();
    float* red = kq;   // 7 * 16 * 64 floats = 7168
    if (ks2 > 0) {
        #pragma unroll
        for (int nt = 0; nt < 4; nt++) {
            const int col = ng * 32 + nt * 8 + 2 * tig;
            *(float2*)&red[((ks2 - 1) * 16 + g) * 64 + col]     = make_float2(pacc[nt][0], pacc[nt][1]);
            *(float2*)&red[((ks2 - 1) * 16 + g + 8) * 64 + col] = make_float2(pacc[nt][2], pacc[nt][3]);
        }
    }
    __syncthreads();
    if (ks2 == 0) {
        #pragma unroll
        for (int nt = 0; nt < 4; nt++) {
            const int col = ng * 32 + nt * 8 + 2 * tig;
            #pragma unroll
            for (int half = 0; half < 2; half++) {
                const int row = g + half * 8;
                float s0 = pacc[nt][half * 2 + 0];
                float s1 = pacc[nt][half * 2 + 1];
                #pragma unroll
                for (int p = 0; p < 7; p++) {
                    s0 += red[(p * 16 + row) * 64 + col];
                    s1 += red[(p * 16 + row) * 64 + col + 1];
                }
                const float inv = sinv[row];
                *(float2*)&out[(size_t)(b * SQ + i0 + row) * EE + h * DH + col] =
                    make_float2(s0 * inv, s1 * inv);
            }
        }
    }
}

// ---------------------------------------------------------------------------
extern "C" void kernel_launch(void* const* d_in, const int* in_sizes, int n_in,
                              void* d_out, int out_size)
{
    const float* x = (const float*)d_in[0];
    const float* W = (const float*)d_in[1];
    float* out = (float*)d_out;

    const long out_elems  = (long)BB * SQ * EE;
    const long attn_elems = (long)BB * HH * SQ * SQ;
    int write_attn = ((long)out_size >= out_elems + attn_elems) ? 1 : 0;
    float* attn = write_attn ? (out + out_elems) : nullptr;

    float *gq, *gk, *gv, *xr, *wr;
    cudaGetSymbolAddress((void**)&gq, g_q);
    cudaGetSymbolAddress((void**)&gk, g_k);
    cudaGetSymbolAddress((void**)&gv, g_v);
    cudaGetSymbolAddress((void**)&xr, g_xr);
    cudaGetSymbolAddress((void**)&wr, g_wr);

    // Pre-round inputs to tf32
    {
        int n4x = GM * GK / 4;
        int n4w = GN * GK / 4;
        round_tf32_kernel<<<(n4x + 255) / 256, 256>>>(x, xr, n4x);
        round_tf32_kernel<<<(n4w + 255) / 256, 256>>>(W, wr, n4w);
    }

    // QKV projection (TF32 tensor cores, raw fragments) + tf32-rounded scatter
    {
        int gemm_smem = 4 * ABUF * (int)sizeof(float);
        cudaFuncSetAttribute(qkv_gemm_tf32, cudaFuncAttributeMaxDynamicSharedMemorySize, gemm_smem);
        dim3 grid(GN / TN, GM / TM);
        qkv_gemm_tf32<<<grid, 256, gemm_smem>>>(xr, wr, gq, gk, gv);
    }

    // Fused attention
    {
        int smem_bytes = (ROWS * SCP + 2 * KTP + ROWS * 68 + 16) * (int)sizeof(float);
        cudaFuncSetAttribute(attn_kernel, cudaFuncAttributeMaxDynamicSharedMemorySize, smem_bytes);
        dim3 grid(SQ / ROWS, HH, BB);
        attn_kernel<<<grid, 512, smem_bytes>>>(gq, gk, gv, out, attn, write_attn);
    }
}

// round 14
// speedup vs baseline: 1.1006x; 1.1006x over previous
#include <cuda_runtime.h>
#include <math.h>
#include <stdint.h>

#define BB 4
#define SQ 2048
#define EE 1024
#define HH 16
#define DH 64
#define ROWS 16
#define KT 128

#define GM (BB*SQ)     // 8192
#define GN (3*EE)      // 3072
#define GK (EE)        // 1024

// GEMM tiling
#define TM 128
#define TN 128
#define TKS 32
#define PAD 36
#define ABUF (TM*PAD)

#define SCP 2052       // sc row pitch (mod 32 banks = 4)
#define KTP 8704       // K tile buffer stride (128*68)
#define VTP 8704       // V tile buffer stride (64*132 = 8448, padded)

// Scratch
__device__ float g_q[(size_t)BB * HH * SQ * DH];
__device__ float g_k[(size_t)BB * HH * SQ * DH];
__device__ float g_v[(size_t)BB * HH * DH * SQ];
__device__ float g_xr[(size_t)GM * GK];     // tf32-rounded x
__device__ float g_wr[(size_t)GN * GK];     // tf32-rounded W

__device__ __forceinline__ uint32_t f2tf32(float x) {
    uint32_t r;
    asm("cvt.rna.tf32.f32 %0, %1;" : "=r"(r) : "f"(x));
    return r;
}
__device__ __forceinline__ float tf32r(float x) { return __uint_as_float(f2tf32(x)); }

__device__ __forceinline__ void stcs4(float* p, float4 v) {
    asm volatile("st.global.cs.v4.f32 [%0], {%1,%2,%3,%4};\n"
                 :: "l"(p), "f"(v.x), "f"(v.y), "f"(v.z), "f"(v.w));
}
__device__ __forceinline__ void stcs2(float* p, float2 v) {
    asm volatile("st.global.cs.v2.f32 [%0], {%1,%2};\n"
                 :: "l"(p), "f"(v.x), "f"(v.y));
}

#define MMA_TF32(acc, a0, a1, a2, a3, b0, b1)                                \
    asm volatile(                                                            \
        "mma.sync.aligned.m16n8k8.row.col.f32.tf32.tf32.f32 "                \
        "{%0,%1,%2,%3}, {%4,%5,%6,%7}, {%8,%9}, {%0,%1,%2,%3};\n"            \
        : "+f"(acc[0]), "+f"(acc[1]), "+f"(acc[2]), "+f"(acc[3])             \
        : "r"(a0), "r"(a1), "r"(a2), "r"(a3), "r"(b0), "r"(b1))

#define CP_ASYNC16(dst, src) \
    asm volatile("cp.async.cg.shared.global [%0], [%1], 16;\n" :: "r"(dst), "l"(src))
#define CP_COMMIT()  asm volatile("cp.async.commit_group;\n" ::)
#define CP_WAIT(n)   asm volatile("cp.async.wait_group %0;\n" :: "n"(n))

// ---------------------------------------------------------------------------
// Pre-round input arrays to tf32 (numerically identical to in-loop cvt).
// ---------------------------------------------------------------------------
__global__ __launch_bounds__(256) void round_tf32_kernel(
    const float* __restrict__ in, float* __restrict__ out, int n4)
{
    int i = blockIdx.x * 256 + threadIdx.x;
    if (i < n4) {
        float4 v = ((const float4*)in)[i];
        v.x = tf32r(v.x); v.y = tf32r(v.y); v.z = tf32r(v.z); v.w = tf32r(v.w);
        ((float4*)out)[i] = v;
    }
}

// ---------------------------------------------------------------------------
// QKV GEMM (TF32): qkv = xr @ Wr^T (pre-rounded), scatter into g_k/g_q/g_v.
// Raw fragment loads, pipelined mainloop. (R13 version — net positive)
// ---------------------------------------------------------------------------
__global__ __launch_bounds__(256, 2) void qkv_gemm_tf32(
    const float* __restrict__ A, const float* __restrict__ W,
    float* __restrict__ gq, float* __restrict__ gk, float* __restrict__ gv)
{
    extern __shared__ float gs[];
    float* As = gs;
    float* Bs = gs + 2 * ABUF;

    const int tid  = threadIdx.x;
    const int lane = tid & 31;
    const int wid  = tid >> 5;
    const int wm   = wid & 3;
    const int wn   = wid >> 2;
    const int g    = lane >> 2;
    const int tig  = lane & 3;
    const int m0   = blockIdx.y * TM;
    const int n0   = blockIdx.x * TN;

    const uint32_t s_base = (uint32_t)__cvta_generic_to_shared(gs);

    float acc[2][8][4] = {};

    auto issue = [&](int s, int buf) {
        const int k0 = s * TKS;
        #pragma unroll
        for (int i = 0; i < 4; i++) {
            int c   = tid + i * 256;
            int row = c >> 3;
            int kc  = (c & 7) * 4;
            const float* srcA = A + (size_t)(m0 + row) * GK + k0 + kc;
            uint32_t dstA = s_base + (uint32_t)(buf * ABUF + row * PAD + kc) * 4u;
            CP_ASYNC16(dstA, srcA);
            const float* srcB = W + (size_t)(n0 + row) * GK + k0 + kc;
            uint32_t dstB = s_base + (uint32_t)(2 * ABUF * 4u) + (uint32_t)(buf * ABUF + row * PAD + kc) * 4u;
            CP_ASYNC16(dstB, srcB);
        }
        CP_COMMIT();
    };

    const int NS = GK / TKS;
    issue(0, 0);

    for (int s = 0; s < NS; s++) {
        const int cur = s & 1;
        CP_WAIT(0);
        __syncthreads();
        if (s + 1 < NS) issue(s + 1, cur ^ 1);

        const float* Ab = As + cur * ABUF + (wm * 32) * PAD;
        const float* Bb = Bs + cur * ABUF + (wn * 64) * PAD;

        #pragma unroll
        for (int kk = 0; kk < TKS; kk += 8) {
            uint32_t bf[8][2];
            #pragma unroll
            for (int nt = 0; nt < 8; nt++) {
                bf[nt][0] = __float_as_uint(Bb[(nt * 8 + g) * PAD + kk + tig]);
                bf[nt][1] = __float_as_uint(Bb[(nt * 8 + g) * PAD + kk + tig + 4]);
            }
            #pragma unroll
            for (int mt = 0; mt < 2; mt++) {
                uint32_t af[4];
                af[0] = __float_as_uint(Ab[(mt * 16 + g) * PAD     + kk + tig]);
                af[1] = __float_as_uint(Ab[(mt * 16 + g + 8) * PAD + kk + tig]);
                af[2] = __float_as_uint(Ab[(mt * 16 + g) * PAD     + kk + tig + 4]);
                af[3] = __float_as_uint(Ab[(mt * 16 + g + 8) * PAD + kk + tig + 4]);
                #pragma unroll
                for (int nt = 0; nt < 8; nt++)
                    MMA_TF32(acc[mt][nt], af[0], af[1], af[2], af[3], bf[nt][0], bf[nt][1]);
            }
        }
    }

    // epilogue: tf32-round, scatter to g_k (chunk 0), g_q (chunk 1), g_v^T (chunk 2)
    #pragma unroll
    for (int mt = 0; mt < 2; mt++) {
        #pragma unroll
        for (int nt = 0; nt < 8; nt++) {
            const int cc    = n0 + wn * 64 + nt * 8 + 2 * tig;
            const int chunk = cc >> 10;
            const int hd    = (cc & 1023) >> 6;
            const int d     = cc & 63;
            #pragma unroll
            for (int half = 0; half < 2; half++) {
                const int r = m0 + wm * 32 + mt * 16 + g + half * 8;
                const int b = r >> 11, srow = r & 2047;
                const float c0 = tf32r(acc[mt][nt][half * 2 + 0]);
                const float c1 = tf32r(acc[mt][nt][half * 2 + 1]);
                const size_t bh = (size_t)(b * HH + hd);
                if (chunk == 0) {
                    *(float2*)&gk[(bh * SQ + srow) * DH + d] = make_float2(c0, c1);
                } else if (chunk == 1) {
                    *(float2*)&gq[(bh * SQ + srow) * DH + d] = make_float2(c0, c1);
                } else {
                    gv[(bh * DH + d) * SQ + srow]     = c0;
                    gv[(bh * DH + d + 1) * SQ + srow] = c1;
                }
            }
        }
    }
}

// ---------------------------------------------------------------------------
// Fused causal ALiBi attention, TF32 MMA.
// R12 pipeline ordering (fill-before-wait, CP_WAIT(1), trailing barrier)
// + strength-reduced fills + streaming attn stores.
// One CTA per (b, h, 16-row query tile). 512 threads = 16 warps.
// ---------------------------------------------------------------------------
__global__ __launch_bounds__(512, 1) void attn_kernel(
    const float* __restrict__ gq, const float* __restrict__ gk,
    const float* __restrict__ gv, float* __restrict__ out,
    float* __restrict__ attn, int write_attn)
{
    extern __shared__ float smem[];
    float* sc   = smem;                    // 16 * SCP
    float* kq   = sc + ROWS * SCP;         // 2*KTP = 17408 floats
    float* qs   = kq + 2 * KTP;            // 16 * 68
    float* sinv = qs + ROWS * 68;          // 16

    const uint32_t s_kq = (uint32_t)__cvta_generic_to_shared(kq);

    const int i0 = (gridDim.x - 1 - blockIdx.x) * ROWS;   // longest tiles first
    const int h  = blockIdx.y;
    const int b  = blockIdx.z;
    const int tid  = threadIdx.x;
    const int lane = tid & 31;
    const int w    = tid >> 5;             // warp 0..15
    const int g    = lane >> 2;            // 0..7
    const int tig  = lane & 3;             // 0..3

    const size_t bh   = (size_t)(b * HH + h);
    const float slope = exp2f(-0.5f * (float)(h + 1));
    const float inv_scale = 1.0f / 32.0f;

    const int jend   = ((i0 + ROWS - 1) / 64 + 1) * 64;   // multiple of 64
    const int ntiles = (jend + KT - 1) / KT;

    // strength-reduced per-thread fill bases
    const float*  gk_base = gk + bh * SQ * DH + tid * 4;
    const uint32_t kdst0  = s_kq + (uint32_t)(((tid >> 4) * 68 + (tid & 15) * 4)) * 4u;
    const float*  gv_base = gv + (bh * DH + (tid >> 5)) * SQ + (tid & 31) * 4;
    const uint32_t vdst0  = s_kq + (uint32_t)(((tid >> 5) * 132 + (tid & 31) * 4)) * 4u;

    auto fill_k = [&](int t, int buf) {
        const int jt = t * KT;
        const int ktile = min(KT, jend - jt);
        const float* src = gk_base + jt * DH;
        uint32_t dst = kdst0 + (uint32_t)(buf * KTP) * 4u;
        const int n = (ktile == KT) ? 4 : 2;
        for (int i = 0; i < n; i++) {
            CP_ASYNC16(dst, src);
            dst += 32u * 68u * 4u;
            src += 2048;
        }
        CP_COMMIT();
    };
    auto fill_v = [&](int t, int buf) {
        const int jt = t * KT;
        const int ktile = min(KT, jend - jt);
        if (ktile == KT) {
            const float* src = gv_base + jt;
            uint32_t dst = vdst0 + (uint32_t)(buf * VTP) * 4u;
            #pragma unroll
            for (int i = 0; i < 4; i++) {
                CP_ASYNC16(dst, src);
                dst += 16u * 132u * 4u;
                src += 16 * SQ;
            }
        } else {
            for (int idx = tid; idx < 64 * 16; idx += 512) {
                int d = idx >> 4, jc = (idx & 15) * 4;
                CP_ASYNC16(s_kq + (uint32_t)(buf * VTP + d * 132 + jc) * 4u,
                           &gv[(bh * DH + d) * SQ + jt + jc]);
            }
        }
        CP_COMMIT();
    };

    // kick off first K tile immediately (overlaps with Q load)
    fill_k(0, 0);

    // --- load Q (16 x 64), pre-rounded tf32 ---
    if (tid < 256) {
        int r = tid >> 4, dc = (tid & 15) * 4;
        float4 v = *(const float4*)&gq[(bh * SQ + i0 + r) * DH + dc];
        *(float4*)&qs[r * 68 + dc] = v;
    }
    __syncthreads();

    // --- preload Q fragments (rows g, g+8), raw bits ---
    uint32_t qa[8][4];
    #pragma unroll
    for (int kk = 0; kk < 8; kk++) {
        qa[kk][0] = __float_as_uint(qs[g * 68       + kk * 8 + tig]);
        qa[kk][1] = __float_as_uint(qs[(g + 8) * 68 + kk * 8 + tig]);
        qa[kk][2] = __float_as_uint(qs[g * 68       + kk * 8 + tig + 4]);
        qa[kk][3] = __float_as_uint(qs[(g + 8) * 68 + kk * 8 + tig + 4]);
    }

    // ======================= scores (MMA, R12 pipeline) =======================
    for (int t = 0; t < ntiles; t++) {
        const int cur = t & 1;
        const int jt  = t * KT;
        const int ktile = min(KT, jend - jt);
        if (t + 1 < ntiles) { fill_k(t + 1, cur ^ 1); CP_WAIT(1); }
        else                { CP_WAIT(0); }
        __syncthreads();

        if (w * 8 < ktile) {
            const float* ktb = kq + cur * KTP + (w * 8 + g) * 68;
            float acc[4] = {};
            #pragma unroll
            for (int kk = 0; kk < 8; kk++) {
                uint32_t b0 = __float_as_uint(ktb[kk * 8 + tig]);
                uint32_t b1 = __float_as_uint(ktb[kk * 8 + tig + 4]);
                MMA_TF32(acc, qa[kk][0], qa[kk][1], qa[kk][2], qa[kk][3], b0, b1);
            }
            const int j0 = jt + w * 8 + 2 * tig;
            #pragma unroll
            for (int half = 0; half < 2; half++) {
                const int row = g + half * 8;
                const int gi  = i0 + row;
                float v0 = (j0     <= gi) ? fmaf(slope, (float)(j0 - gi),     acc[half*2+0] * inv_scale) : -INFINITY;
                float v1 = (j0 + 1 <= gi) ? fmaf(slope, (float)(j0 + 1 - gi), acc[half*2+1] * inv_scale) : -INFINITY;
                *(float2*)&sc[row * SCP + j0] = make_float2(v0, v1);
            }
        }
        __syncthreads();
    }

    // prefetch first V tile; it lands while softmax runs
    fill_v(0, 0);

    // ======================= softmax (warp w owns row w) =======================
    {
        float* row = sc + w * SCP;
        float mx = -INFINITY;
        for (int j = lane * 4; j < jend; j += 128) {
            float4 v = *(const float4*)(row + j);
            mx = fmaxf(mx, fmaxf(fmaxf(v.x, v.y), fmaxf(v.z, v.w)));
        }
        #pragma unroll
        for (int o = 16; o; o >>= 1) mx = fmaxf(mx, __shfl_xor_sync(0xffffffffu, mx, o));
        float sum = 0.f;
        for (int j = lane * 4; j < jend; j += 128) {
            float4 v = *(const float4*)(row + j);
            v.x = __expf(v.x - mx); v.y = __expf(v.y - mx);
            v.z = __expf(v.z - mx); v.w = __expf(v.w - mx);
            *(float4*)(row + j) = v;
            sum += v.x + v.y + v.z + v.w;
        }
        #pragma unroll
        for (int o = 16; o; o >>= 1) sum += __shfl_xor_sync(0xffffffffu, sum, o);
        const float inv = 1.0f / sum;
        if (lane == 0) sinv[w] = inv;

        if (write_attn) {
            float* arow = attn + (bh * SQ + i0 + w) * SQ;
            for (int j = lane * 4; j < jend; j += 128) {
                float4 v = *(const float4*)(row + j);
                v.x *= inv; v.y *= inv; v.z *= inv; v.w *= inv;
                stcs4(arow + j, v);
            }
            const float4 z = make_float4(0.f, 0.f, 0.f, 0.f);
            for (int j = jend + lane * 4; j < SQ; j += 128)
                stcs4(arow + j, z);
        }
    }

    // ======================= PV (MMA, R12 pipeline) =======================
    // warps: ks2 = w>>1 (8 key slabs of 16), ng = w&1 (d half of 32).
    const int ks2 = w >> 1;
    const int ng  = w & 1;
    float pacc[4][4] = {};

    for (int t = 0; t < ntiles; t++) {
        const int cur = t & 1;
        const int jt  = t * KT;
        const int ktile = min(KT, jend - jt);
        __syncthreads();                      // all reads of buf cur^1 done (prev MMA / softmax)
        if (t + 1 < ntiles) { fill_v(t + 1, cur ^ 1); CP_WAIT(1); }
        else                { CP_WAIT(0); }
        __syncthreads();

        const int kb2 = ks2 * 16;
        if (kb2 < ktile) {
            const float* vtb = kq + cur * VTP;
            #pragma unroll
            for (int kk2 = 0; kk2 < 2; kk2++) {
                const int kloc = kb2 + kk2 * 8;
                uint32_t af0 = f2tf32(sc[g * SCP       + jt + kloc + tig]);
                uint32_t af1 = f2tf32(sc[(g + 8) * SCP + jt + kloc + tig]);
                uint32_t af2 = f2tf32(sc[g * SCP       + jt + kloc + tig + 4]);
                uint32_t af3 = f2tf32(sc[(g + 8) * SCP + jt + kloc + tig + 4]);
                #pragma unroll
                for (int nt = 0; nt < 4; nt++) {
                    const int d = ng * 32 + nt * 8 + g;
                    uint32_t b0 = __float_as_uint(vtb[d * 132 + kloc + tig]);
                    uint32_t b1 = __float_as_uint(vtb[d * 132 + kloc + tig + 4]);
                    MMA_TF32(pacc[nt], af0, af1, af2, af3, b0, b1);
                }
            }
        }
    }

    // --- reduce partials across the 8 key-slab warps (overlay on kq) ---
    __syncthreads();
    float* red = kq;   // 7 * 16 * 64 floats = 7168
    if (ks2 > 0) {
        #pragma unroll
        for (int nt = 0; nt < 4; nt++) {
            const int col = ng * 32 + nt * 8 + 2 * tig;
            *(float2*)&red[((ks2 - 1) * 16 + g) * 64 + col]     = make_float2(pacc[nt][0], pacc[nt][1]);
            *(float2*)&red[((ks2 - 1) * 16 + g + 8) * 64 + col] = make_float2(pacc[nt][2], pacc[nt][3]);
        }
    }
    __syncthreads();
    if (ks2 == 0) {
        #pragma unroll
        for (int nt = 0; nt < 4; nt++) {
            const int col = ng * 32 + nt * 8 + 2 * tig;
            #pragma unroll
            for (int half = 0; half < 2; half++) {
                const int row = g + half * 8;
                float s0 = pacc[nt][half * 2 + 0];
                float s1 = pacc[nt][half * 2 + 1];
                #pragma unroll
                for (int p = 0; p < 7; p++) {
                    s0 += red[(p * 16 + row) * 64 + col];
                    s1 += red[(p * 16 + row) * 64 + col + 1];
                }
                const float inv = sinv[row];
                *(float2*)&out[(size_t)(b * SQ + i0 + row) * EE + h * DH + col] =
                    make_float2(s0 * inv, s1 * inv);
            }
        }
    }
}

// ---------------------------------------------------------------------------
extern "C" void kernel_launch(void* const* d_in, const int* in_sizes, int n_in,
                              void* d_out, int out_size)
{
    const float* x = (const float*)d_in[0];
    const float* W = (const float*)d_in[1];
    float* out = (float*)d_out;

    const long out_elems  = (long)BB * SQ * EE;
    const long attn_elems = (long)BB * HH * SQ * SQ;
    int write_attn = ((long)out_size >= out_elems + attn_elems) ? 1 : 0;
    float* attn = write_attn ? (out + out_elems) : nullptr;

    float *gq, *gk, *gv, *xr, *wr;
    cudaGetSymbolAddress((void**)&gq, g_q);
    cudaGetSymbolAddress((void**)&gk, g_k);
    cudaGetSymbolAddress((void**)&gv, g_v);
    cudaGetSymbolAddress((void**)&xr, g_xr);
    cudaGetSymbolAddress((void**)&wr, g_wr);

    // Pre-round inputs to tf32
    {
        int n4x = GM * GK / 4;
        int n4w = GN * GK / 4;
        round_tf32_kernel<<<(n4x + 255) / 256, 256>>>(x, xr, n4x);
        round_tf32_kernel<<<(n4w + 255) / 256, 256>>>(W, wr, n4w);
    }

    // QKV projection (TF32 tensor cores, raw fragments)
    {
        int gemm_smem = 4 * ABUF * (int)sizeof(float);
        cudaFuncSetAttribute(qkv_gemm_tf32, cudaFuncAttributeMaxDynamicSharedMemorySize, gemm_smem);
        dim3 grid(GN / TN, GM / TM);
        qkv_gemm_tf32<<<grid, 256, gemm_smem>>>(xr, wr, gq, gk, gv);
    }

    // Fused attention
    {
        int smem_bytes = (ROWS * SCP + 2 * KTP + ROWS * 68 + 16) * (int)sizeof(float);
        cudaFuncSetAttribute(attn_kernel, cudaFuncAttributeMaxDynamicSharedMemorySize, smem_bytes);
        dim3 grid(SQ / ROWS, HH, BB);
        attn_kernel<<<grid, 512, smem_bytes>>>(gq, gk, gv, out, attn, write_attn);
    }
}